// round 3
// baseline (speedup 1.0000x reference)
#include <cuda_runtime.h>
#include <cstdint>

#define B_DIM 8192
#define D_DIM 768
#define L_DIM 16384
#define K_TOP 100
#define DELTA_BAND 2.5e-3f
#define UNC_CAP 192

// ============================ device scratch ============================
__device__ float g_Ap[(size_t)B_DIM * D_DIM];   // tf32-rounded A, panel layout [B/128][D][128]
__device__ float g_Xb[(size_t)B_DIM * D_DIM];   // exact fp32 (xn - pre_bias), row-major
__device__ float g_Wr[(size_t)D_DIM * L_DIM];   // W_enc tf32-rounded, [D][L]
__device__ float g_WT[(size_t)L_DIM * D_DIM];   // W_enc exact transpose, [L][D]
__device__ float g_mu[B_DIM];
__device__ float g_std[B_DIM];
__device__ int   g_tidx[B_DIM * K_TOP];
__device__ float g_tval[B_DIM * K_TOP];

// ============================ helpers ============================
__device__ __forceinline__ uint32_t smem_to_u32(const void* p) {
    uint32_t a;
    asm("{ .reg .u64 t; cvta.to.shared.u64 t, %1; cvt.u32.u64 %0, t; }" : "=r"(a) : "l"(p));
    return a;
}
__device__ __forceinline__ float tf32r(float x) {
    uint32_t u;
    asm("cvt.rna.tf32.f32 %0, %1;" : "=r"(u) : "f"(x));
    return __uint_as_float(u);
}
__device__ __forceinline__ void cp16(uint32_t saddr, const void* g) {
    asm volatile("cp.async.cg.shared.global [%0], [%1], 16;" :: "r"(saddr), "l"(g));
}
#define CP_COMMIT() asm volatile("cp.async.commit_group;" ::: "memory")
#define CP_WAIT2()  asm volatile("cp.async.wait_group 2;" ::: "memory")

__device__ __forceinline__ void mma_tf32(float* d, const uint32_t* a, const uint32_t* b) {
    asm volatile(
        "mma.sync.aligned.m16n8k8.row.col.f32.tf32.tf32.f32 "
        "{%0,%1,%2,%3}, {%4,%5,%6,%7}, {%8,%9}, {%0,%1,%2,%3};"
        : "+f"(d[0]), "+f"(d[1]), "+f"(d[2]), "+f"(d[3])
        : "r"(a[0]), "r"(a[1]), "r"(a[2]), "r"(a[3]), "r"(b[0]), "r"(b[1]));
}

__device__ __forceinline__ float key_to_float(uint32_t k) {
    uint32_t u = (k & 0x80000000u) ? (k & 0x7FFFFFFFu) : ~k;
    return __uint_as_float(u);
}
__device__ __forceinline__ uint32_t float_to_key(float f) {
    uint32_t u = __float_as_uint(f);
    return (u & 0x80000000u) ? ~u : (u | 0x80000000u);
}

// ============================ kernel 1: normalize ============================
__global__ void __launch_bounds__(256) normalize_kernel(const float* __restrict__ x,
                                                        const float* __restrict__ pre_bias) {
    __shared__ float rs[8], rs2[8], bc[2];
    int row = blockIdx.x, t = threadIdx.x;
    const float* xr = x + (size_t)row * D_DIM;
    float v0 = xr[t], v1 = xr[t + 256], v2 = xr[t + 512];
    float s = v0 + v1 + v2;
    float s2 = v0 * v0 + v1 * v1 + v2 * v2;
    for (int o = 16; o; o >>= 1) {
        s  += __shfl_down_sync(0xFFFFFFFFu, s,  o);
        s2 += __shfl_down_sync(0xFFFFFFFFu, s2, o);
    }
    if ((t & 31) == 0) { rs[t >> 5] = s; rs2[t >> 5] = s2; }
    __syncthreads();
    if (t == 0) {
        float a = 0.f, b = 0.f;
        for (int w = 0; w < 8; w++) { a += rs[w]; b += rs2[w]; }
        float mu = a / (float)D_DIM;
        float var = b / (float)D_DIM - mu * mu;
        float sd = sqrtf(fmaxf(var, 0.0f));
        bc[0] = mu; bc[1] = sd;
        g_mu[row] = mu; g_std[row] = sd;
    }
    __syncthreads();
    float mu = bc[0], sd = bc[1];
    float inv = 1.0f / (sd + 1e-5f);
    float e0 = (v0 - mu) * inv - pre_bias[t];
    float e1 = (v1 - mu) * inv - pre_bias[t + 256];
    float e2 = (v2 - mu) * inv - pre_bias[t + 512];
    float* Xr = g_Xb + (size_t)row * D_DIM;
    Xr[t] = e0; Xr[t + 256] = e1; Xr[t + 512] = e2;
    float* Ap = g_Ap + (size_t)(row >> 7) * ((size_t)D_DIM * 128) + (row & 127);
    Ap[(size_t)t * 128]         = tf32r(e0);
    Ap[(size_t)(t + 256) * 128] = tf32r(e1);
    Ap[(size_t)(t + 512) * 128] = tf32r(e2);
}

// ============================ kernel 2a: pre-round W_enc (tf32) ============================
__global__ void __launch_bounds__(256) roundW_kernel(const float* __restrict__ W) {
    size_t i = ((size_t)blockIdx.x * 256 + threadIdx.x) * 4;
    float4 v = *(const float4*)(W + i);
    v.x = tf32r(v.x); v.y = tf32r(v.y); v.z = tf32r(v.z); v.w = tf32r(v.w);
    *(float4*)(g_Wr + i) = v;
}

// ============================ kernel 2b: exact transpose W_enc ============================
__global__ void __launch_bounds__(256) transpose_kernel(const float* __restrict__ W) {
    __shared__ float tile[32][33];
    int bx = blockIdx.x, by = blockIdx.y;
    int tx = threadIdx.x & 31, ty = threadIdx.x >> 5;
    #pragma unroll
    for (int j = 0; j < 32; j += 8)
        tile[ty + j][tx] = W[(size_t)(by * 32 + ty + j) * L_DIM + bx * 32 + tx];
    __syncthreads();
    #pragma unroll
    for (int j = 0; j < 32; j += 8)
        g_WT[(size_t)(bx * 32 + ty + j) * D_DIM + by * 32 + tx] = tile[tx][ty + j];
}

// ============================ kernel 3: encode GEMM (tf32 mma) ============================
#define KC 16
#define NCHUNK (D_DIM / KC)
#define NSTAGE 4
#define A_STRIDE 136
#define B_STRIDE 264
#define A_STAGE_BYTES (KC * A_STRIDE * 4)
#define B_STAGE_BYTES (KC * B_STRIDE * 4)
#define A_OFF 0
#define B_OFF (A_STAGE_BYTES * NSTAGE)
#define GEMM_SMEM (A_STAGE_BYTES * NSTAGE + B_STAGE_BYTES * NSTAGE)

__global__ void __launch_bounds__(256, 1) gemm_kernel(const float* __restrict__ lat_bias,
                                                      float* __restrict__ C) {
    extern __shared__ char smem[];
    uint32_t sb = smem_to_u32(smem);
    int t = threadIdx.x, wid = t >> 5, lane = t & 31;
    int wm = wid & 1, wn = wid >> 1;
    int r4 = lane >> 2, cs = lane & 3;
    int m0 = blockIdx.y * 128, n0 = blockIdx.x * 256;
    const float* Apanel = g_Ap + (size_t)(m0 >> 7) * ((size_t)D_DIM * 128);
    const float* Wb = g_Wr + n0;

    auto issue = [&](int c, int buf) {
        uint32_t abase = sb + A_OFF + buf * A_STAGE_BYTES;
        uint32_t bbase = sb + B_OFF + buf * B_STAGE_BYTES;
        int k0 = c * KC;
        #pragma unroll
        for (int i = 0; i < 2; i++) {
            int idx = t + i * 256;
            int k = idx >> 5, seg = idx & 31;
            cp16(abase + k * (A_STRIDE * 4) + seg * 16,
                 Apanel + (size_t)(k0 + k) * 128 + seg * 4);
        }
        #pragma unroll
        for (int i = 0; i < 4; i++) {
            int idx = t + i * 256;
            int k = idx >> 6, seg = idx & 63;
            cp16(bbase + k * (B_STRIDE * 4) + seg * 16,
                 Wb + (size_t)(k0 + k) * L_DIM + seg * 4);
        }
    };

    #pragma unroll
    for (int c = 0; c < NSTAGE - 1; c++) { issue(c, c); CP_COMMIT(); }

    float acc[4][8][4];
    #pragma unroll
    for (int mt = 0; mt < 4; mt++)
        #pragma unroll
        for (int nt = 0; nt < 8; nt++)
            #pragma unroll
            for (int q = 0; q < 4; q++) acc[mt][nt][q] = 0.f;

    for (int c = 0; c < NCHUNK; c++) {
        CP_WAIT2();
        __syncthreads();
        if (c + NSTAGE - 1 < NCHUNK) issue(c + NSTAGE - 1, (c + NSTAGE - 1) & (NSTAGE - 1));
        CP_COMMIT();

        const float* As = (const float*)(smem + A_OFF + (c & (NSTAGE - 1)) * A_STAGE_BYTES);
        const float* Bs = (const float*)(smem + B_OFF + (c & (NSTAGE - 1)) * B_STAGE_BYTES);
        #pragma unroll
        for (int k8 = 0; k8 < 2; k8++) {
            uint32_t a[4][4], b[8][2];
            #pragma unroll
            for (int mt = 0; mt < 4; mt++) {
                const float* base = As + (k8 * 8 + cs) * A_STRIDE + wm * 64 + mt * 16 + r4;
                a[mt][0] = __float_as_uint(base[0]);
                a[mt][1] = __float_as_uint(base[8]);
                a[mt][2] = __float_as_uint(base[4 * A_STRIDE]);
                a[mt][3] = __float_as_uint(base[4 * A_STRIDE + 8]);
            }
            #pragma unroll
            for (int nt = 0; nt < 8; nt++) {
                const float* base = Bs + (k8 * 8 + cs) * B_STRIDE + wn * 64 + nt * 8 + r4;
                b[nt][0] = __float_as_uint(base[0]);
                b[nt][1] = __float_as_uint(base[4 * B_STRIDE]);
            }
            #pragma unroll
            for (int mt = 0; mt < 4; mt++)
                #pragma unroll
                for (int nt = 0; nt < 8; nt++)
                    mma_tf32(acc[mt][nt], a[mt], b[nt]);
        }
        __syncthreads();
    }

    #pragma unroll
    for (int mt = 0; mt < 4; mt++) {
        int m = m0 + wm * 64 + mt * 16 + r4;
        #pragma unroll
        for (int nt = 0; nt < 8; nt++) {
            int n = n0 + wn * 64 + nt * 8 + cs * 2;
            float2 bb = *(const float2*)(lat_bias + n);
            float2 v0 = make_float2(acc[mt][nt][0] + bb.x, acc[mt][nt][1] + bb.y);
            float2 v1 = make_float2(acc[mt][nt][2] + bb.x, acc[mt][nt][3] + bb.y);
            *(float2*)(C + (size_t)m * L_DIM + n) = v0;
            *(float2*)(C + (size_t)(m + 8) * L_DIM + n) = v1;
        }
    }
}

// ============================ kernel 4: top-k with exact boundary refinement ============================
__global__ void __launch_bounds__(256) topk_kernel(const float* __restrict__ P,
                                                   const float* __restrict__ lat_bias,
                                                   float* __restrict__ latents) {
    extern __shared__ uint32_t keys[];  // 16384 u32 = 64KB
    __shared__ int s_red[9];
    __shared__ int s_cnt_sel, s_cnt_eq, s_cnt_unc, s_cnt_fin;
    __shared__ uint32_t sel_key[K_TOP];
    __shared__ int      sel_idx[K_TOP];
    __shared__ uint32_t s_eqk[512];
    __shared__ int      s_eqi[512];
    __shared__ int      unc_idx[UNC_CAP];
    __shared__ float    unc_ex[UNC_CAP];
    __shared__ int      fin_idx[K_TOP];
    __shared__ float    fin_val[K_TOP];
    __shared__ uint32_t s_klo, s_khi;

    int row = blockIdx.x, t = threadIdx.x, lane = t & 31;
    const float* Pr = P + (size_t)row * L_DIM;

    #pragma unroll 8
    for (int i = 0; i < 64; i++)
        keys[t + (i << 8)] = float_to_key(Pr[t + (i << 8)]);
    if (t == 0) { s_cnt_sel = 0; s_cnt_eq = 0; s_cnt_unc = 0; s_cnt_fin = 0; }
    __syncthreads();

    // binary search on top-16 key bits: largest T16 with count(key16 >= T16) >= K
    uint32_t lo = 0, hi = 0xFFFFu;
    while (lo < hi) {
        uint32_t mid = lo + (hi - lo + 1) / 2;
        int c_local = 0;
        #pragma unroll 8
        for (int i = 0; i < 64; i++)
            c_local += (int)((keys[t + (i << 8)] >> 16) >= mid);
        for (int o = 16; o; o >>= 1) c_local += __shfl_down_sync(0xFFFFFFFFu, c_local, o);
        if ((t & 31) == 0) s_red[t >> 5] = c_local;
        __syncthreads();
        if (t < 32) {
            int v = (t < 8) ? s_red[t] : 0;
            for (int o = 4; o; o >>= 1) v += __shfl_down_sync(0xFFFFFFFFu, v, o);
            if (t == 0) s_red[8] = v;
        }
        __syncthreads();
        int total = s_red[8];
        __syncthreads();
        if (total >= K_TOP) lo = mid; else hi = mid - 1;
    }
    uint32_t T16 = lo;

    // strict-above -> selected; equal-prefix -> candidate list
    #pragma unroll 4
    for (int i = 0; i < 64; i++) {
        int idx = t + (i << 8);
        uint32_t k = keys[idx];
        uint32_t k16 = k >> 16;
        if (k16 > T16) {
            int p = atomicAdd(&s_cnt_sel, 1);
            sel_key[p] = k; sel_idx[p] = idx;
        } else if (k16 == T16) {
            int p = atomicAdd(&s_cnt_eq, 1);
            if (p < 512) { s_eqk[p] = k; s_eqi[p] = idx; }
        }
    }
    __syncthreads();
    if (t == 0) {
        int Ccnt = s_cnt_sel;          // < K_TOP by construction
        int R = K_TOP - Ccnt;          // >= 1 by construction
        int E = s_cnt_eq < 512 ? s_cnt_eq : 512;
        for (int a = 1; a < E; a++) {  // key desc, index asc
            uint32_t kk = s_eqk[a]; int ii = s_eqi[a]; int b = a - 1;
            while (b >= 0 && (s_eqk[b] < kk || (s_eqk[b] == kk && s_eqi[b] > ii))) {
                s_eqk[b + 1] = s_eqk[b]; s_eqi[b + 1] = s_eqi[b]; b--;
            }
            s_eqk[b + 1] = kk; s_eqi[b + 1] = ii;
        }
        for (int j = 0; j < R; j++) { sel_key[Ccnt + j] = s_eqk[j]; sel_idx[Ccnt + j] = s_eqi[j]; }
        float v100 = key_to_float(s_eqk[R - 1]);       // 100th approx value
        s_klo = float_to_key(v100 - DELTA_BAND);
        s_khi = float_to_key(v100 + DELTA_BAND);
    }
    __syncthreads();
    uint32_t klo = s_klo, khi = s_khi;

    // uncertainty band sweep
    #pragma unroll 4
    for (int i = 0; i < 64; i++) {
        int idx = t + (i << 8);
        uint32_t k = keys[idx];
        if (k >= klo && k <= khi) {
            int p = atomicAdd(&s_cnt_unc, 1);
            if (p < UNC_CAP) unc_idx[p] = idx;
        }
    }
    // clear winners (approx value safely above band) go straight to final
    if (t < K_TOP) {
        if (sel_key[t] > khi) {
            int p = atomicAdd(&s_cnt_fin, 1);
            fin_idx[p] = sel_idx[t]; fin_val[p] = key_to_float(sel_key[t]);
        }
    }
    __syncthreads();
    int U = s_cnt_unc < UNC_CAP ? s_cnt_unc : UNC_CAP;
    int C = s_cnt_fin;
    int need = K_TOP - C; if (need > U) need = U;

    // exact recompute for band members: warp-per-candidate, Neumaier-compensated dot
    const float* Xr = g_Xb + (size_t)row * D_DIM;
    for (int c = (t >> 5); c < U; c += 8) {
        const float* w = g_WT + (size_t)unc_idx[c] * D_DIM;
        float s = 0.f, comp = 0.f;
        for (int d = lane; d < D_DIM; d += 32) {
            float prod = Xr[d] * w[d];
            float tn = s + prod;
            if (fabsf(s) >= fabsf(prod)) comp += (s - tn) + prod;
            else                         comp += (prod - tn) + s;
            s = tn;
        }
        s += comp;
        for (int o = 16; o; o >>= 1) s += __shfl_xor_sync(0xFFFFFFFFu, s, o);
        if (lane == 0) unc_ex[c] = s + lat_bias[unc_idx[c]];
    }
    __syncthreads();
    if (t == 0) {
        for (int a = 1; a < U; a++) {   // exact desc, index asc
            float vv = unc_ex[a]; int ii = unc_idx[a]; int b = a - 1;
            while (b >= 0 && (unc_ex[b] < vv || (unc_ex[b] == vv && unc_idx[b] > ii))) {
                unc_ex[b + 1] = unc_ex[b]; unc_idx[b + 1] = unc_idx[b]; b--;
            }
            unc_ex[b + 1] = vv; unc_idx[b + 1] = ii;
        }
        for (int q = 0; q < need; q++) {
            fin_idx[C + q] = unc_idx[q]; fin_val[C + q] = unc_ex[q];
        }
        s_cnt_fin = C + need;
    }
    __syncthreads();

    // deterministic scatter: rank by index ascending
    int F = s_cnt_fin;
    if (t < F) {
        int my = fin_idx[t]; float v = fin_val[t];
        int r = 0;
        for (int q = 0; q < F; q++) r += (int)(fin_idx[q] < my);
        g_tidx[row * K_TOP + r] = my;
        g_tval[row * K_TOP + r] = v;
        latents[(size_t)row * L_DIM + my] = v;
    }
}

// ============================ kernel 5: sparse decode ============================
__global__ void __launch_bounds__(256) decode_kernel(const float* __restrict__ Wd,
                                                     const float* __restrict__ pre_bias,
                                                     float* __restrict__ recons) {
    __shared__ int sidx[K_TOP];
    __shared__ float sval[K_TOP];
    int row = blockIdx.x, t = threadIdx.x;
    if (t < K_TOP) { sidx[t] = g_tidx[row * K_TOP + t]; sval[t] = g_tval[row * K_TOP + t]; }
    __syncthreads();
    float a0 = 0.f, a1 = 0.f, a2 = 0.f;
    #pragma unroll 4
    for (int j = 0; j < K_TOP; j++) {
        const float* w = Wd + (size_t)sidx[j] * D_DIM;
        float v = sval[j];
        a0 += v * __ldg(w + t);
        a1 += v * __ldg(w + t + 256);
        a2 += v * __ldg(w + t + 512);
    }
    float sd = g_std[row], mu = g_mu[row];
    float* Rr = recons + (size_t)row * D_DIM;
    Rr[t]       = (a0 + pre_bias[t])       * sd + mu;
    Rr[t + 256] = (a1 + pre_bias[t + 256]) * sd + mu;
    Rr[t + 512] = (a2 + pre_bias[t + 512]) * sd + mu;
}

// ============================ launch ============================
extern "C" void kernel_launch(void* const* d_in, const int* in_sizes, int n_in,
                              void* d_out, int out_size) {
    const float* x        = (const float*)d_in[0];
    const float* pre_bias = (const float*)d_in[1];
    const float* lat_bias = (const float*)d_in[2];
    const float* W_enc    = (const float*)d_in[3];
    const float* W_dec    = (const float*)d_in[4];

    float* outP = (float*)d_out;
    float* outL = outP + (size_t)B_DIM * L_DIM;
    float* outR = outL + (size_t)B_DIM * L_DIM;

    cudaFuncSetAttribute(gemm_kernel, cudaFuncAttributeMaxDynamicSharedMemorySize, GEMM_SMEM);
    cudaFuncSetAttribute(topk_kernel, cudaFuncAttributeMaxDynamicSharedMemorySize, 65536);

    normalize_kernel<<<B_DIM, 256>>>(x, pre_bias);
    roundW_kernel<<<(D_DIM * L_DIM) / (256 * 4), 256>>>(W_enc);
    transpose_kernel<<<dim3(L_DIM / 32, D_DIM / 32), 256>>>(W_enc);
    gemm_kernel<<<dim3(L_DIM / 256, B_DIM / 128), 256, GEMM_SMEM>>>(lat_bias, outP);
    cudaMemsetAsync(outL, 0, (size_t)B_DIM * L_DIM * sizeof(float), 0);
    topk_kernel<<<B_DIM, 256, 65536>>>(outP, lat_bias, outL);
    decode_kernel<<<B_DIM, 256>>>(W_dec, pre_bias, outR);
}

// round 4
// speedup vs baseline: 1.1228x; 1.1228x over previous
#include <cuda_runtime.h>
#include <cstdint>

#define B_DIM 8192
#define D_DIM 768
#define L_DIM 16384
#define K_TOP 100
#define DELTA_BAND 2.5e-3f
#define UNC_CAP 192

// ============================ device scratch ============================
// A in MMA-fragment order: [panel 64][oct 96][mb 8][lane 32] x float4 quads
__device__ float g_Af[(size_t)B_DIM * D_DIM];
// W_enc in MMA-fragment order: [oct 96][nb8 2048][lane 32] x float2 pairs
__device__ float g_Wf[(size_t)D_DIM * L_DIM];
__device__ float g_Xb[(size_t)B_DIM * D_DIM];   // exact fp32 (xn - pre_bias), row-major
__device__ float g_WT[(size_t)L_DIM * D_DIM];   // W_enc exact transpose, [L][D]
__device__ float g_mu[B_DIM];
__device__ float g_std[B_DIM];
__device__ int   g_tidx[B_DIM * K_TOP];
__device__ float g_tval[B_DIM * K_TOP];

// ============================ helpers ============================
__device__ __forceinline__ uint32_t smem_to_u32(const void* p) {
    uint32_t a;
    asm("{ .reg .u64 t; cvta.to.shared.u64 t, %1; cvt.u32.u64 %0, t; }" : "=r"(a) : "l"(p));
    return a;
}
__device__ __forceinline__ float tf32r(float x) {
    uint32_t u;
    asm("cvt.rna.tf32.f32 %0, %1;" : "=r"(u) : "f"(x));
    return __uint_as_float(u);
}
__device__ __forceinline__ void cp16(uint32_t saddr, const void* g) {
    asm volatile("cp.async.cg.shared.global [%0], [%1], 16;" :: "r"(saddr), "l"(g));
}
#define CP_COMMIT() asm volatile("cp.async.commit_group;" ::: "memory")
#define CP_WAIT1()  asm volatile("cp.async.wait_group 1;" ::: "memory")

__device__ __forceinline__ void mma_tf32(float* d, const uint32_t* a, const uint32_t* b) {
    asm volatile(
        "mma.sync.aligned.m16n8k8.row.col.f32.tf32.tf32.f32 "
        "{%0,%1,%2,%3}, {%4,%5,%6,%7}, {%8,%9}, {%0,%1,%2,%3};"
        : "+f"(d[0]), "+f"(d[1]), "+f"(d[2]), "+f"(d[3])
        : "r"(a[0]), "r"(a[1]), "r"(a[2]), "r"(a[3]), "r"(b[0]), "r"(b[1]));
}

__device__ __forceinline__ float key_to_float(uint32_t k) {
    uint32_t u = (k & 0x80000000u) ? (k & 0x7FFFFFFFu) : ~k;
    return __uint_as_float(u);
}
__device__ __forceinline__ uint32_t float_to_key(float f) {
    uint32_t u = __float_as_uint(f);
    return (u & 0x80000000u) ? ~u : (u | 0x80000000u);
}

// ============================ kernel 1: normalize ============================
// writes g_Xb (exact) and g_Af (tf32, fragment order)
__global__ void __launch_bounds__(256) normalize_kernel(const float* __restrict__ x,
                                                        const float* __restrict__ pre_bias) {
    __shared__ float rs[8], rs2[8], bc[2];
    int row = blockIdx.x, t = threadIdx.x;
    const float* xr = x + (size_t)row * D_DIM;
    float v0 = xr[t], v1 = xr[t + 256], v2 = xr[t + 512];
    float s = v0 + v1 + v2;
    float s2 = v0 * v0 + v1 * v1 + v2 * v2;
    for (int o = 16; o; o >>= 1) {
        s  += __shfl_down_sync(0xFFFFFFFFu, s,  o);
        s2 += __shfl_down_sync(0xFFFFFFFFu, s2, o);
    }
    if ((t & 31) == 0) { rs[t >> 5] = s; rs2[t >> 5] = s2; }
    __syncthreads();
    if (t == 0) {
        float a = 0.f, b = 0.f;
        for (int w = 0; w < 8; w++) { a += rs[w]; b += rs2[w]; }
        float mu = a / (float)D_DIM;
        float var = b / (float)D_DIM - mu * mu;
        float sd = sqrtf(fmaxf(var, 0.0f));
        bc[0] = mu; bc[1] = sd;
        g_mu[row] = mu; g_std[row] = sd;
    }
    __syncthreads();
    float mu = bc[0], sd = bc[1];
    float inv = 1.0f / (sd + 1e-5f);
    int p = row >> 7, rloc = row & 127;
    int mb = rloc >> 4, r4 = rloc & 7, hi = (rloc >> 3) & 1;
    size_t pbase = ((size_t)p * 96) * 1024 + (size_t)mb * 128 + (size_t)r4 * 16 + hi;
    float* Xr = g_Xb + (size_t)row * D_DIM;
    #pragma unroll
    for (int j = 0; j < 3; j++) {
        int k = t + j * 256;
        float v = (j == 0 ? v0 : (j == 1 ? v1 : v2));
        float e = (v - mu) * inv - pre_bias[k];
        Xr[k] = e;
        int oct = k >> 3, kl = k & 7, cs = kl & 3, khi = kl >> 2;
        g_Af[pbase + (size_t)oct * 1024 + cs * 4 + 2 * khi] = tf32r(e);
    }
}

// ============================ kernel 2a: pack W_enc (tf32, fragment order) ============================
// grid (96, 64): block = one octet (8 k-rows) x 256 n columns
__global__ void __launch_bounds__(256) packW_kernel(const float* __restrict__ W) {
    __shared__ float s[8 * 256];
    int oct = blockIdx.x, nb = blockIdx.y, t = threadIdx.x;
    #pragma unroll
    for (int r = 0; r < 8; r++)
        s[r * 256 + t] = tf32r(W[(size_t)(oct * 8 + r) * L_DIM + nb * 256 + t]);
    __syncthreads();
    float* out = g_Wf + ((size_t)oct * 2048 + (size_t)nb * 32) * 64;
    #pragma unroll
    for (int j = 0; j < 4; j++) {
        int pr = t * 4 + j;
        int nb8l = pr >> 5, r4 = (pr >> 2) & 7, cs = pr & 3;
        int n = nb8l * 8 + r4;
        out[pr * 2 + 0] = s[cs * 256 + n];
        out[pr * 2 + 1] = s[(cs + 4) * 256 + n];
    }
}

// ============================ kernel 2b: exact transpose W_enc ============================
__global__ void __launch_bounds__(256) transpose_kernel(const float* __restrict__ W) {
    __shared__ float tile[32][33];
    int bx = blockIdx.x, by = blockIdx.y;
    int tx = threadIdx.x & 31, ty = threadIdx.x >> 5;
    #pragma unroll
    for (int j = 0; j < 32; j += 8)
        tile[ty + j][tx] = W[(size_t)(by * 32 + ty + j) * L_DIM + bx * 32 + tx];
    __syncthreads();
    #pragma unroll
    for (int j = 0; j < 32; j += 8)
        g_WT[(size_t)(bx * 32 + ty + j) * D_DIM + by * 32 + tx] = tile[tx][ty + j];
}

// ============================ kernel 3: encode GEMM (tf32 mma, fragment layouts) ============================
#define KC 32
#define NCHUNK (D_DIM / KC)              // 24
#define NSTAGE 3
#define STAGE_BYTES 49152                // A 16KB + B 32KB
#define B_IN_STAGE 16384
#define GEMM_SMEM (NSTAGE * STAGE_BYTES) // 147456

__global__ void __launch_bounds__(256, 1) gemm_kernel(const float* __restrict__ lat_bias,
                                                      float* __restrict__ C) {
    extern __shared__ char smem[];
    uint32_t sb = smem_to_u32(smem);
    int t = threadIdx.x, wid = t >> 5, lane = t & 31;
    int wm = wid & 1, wn = wid >> 1;
    int r4 = lane >> 2, cs = lane & 3;
    int m0 = blockIdx.y * 128, n0 = blockIdx.x * 256;
    int panel = m0 >> 7, nb0 = n0 >> 3;

    auto issue = [&](int c, int slot) {
        uint32_t dst = sb + slot * STAGE_BYTES;
        const float* Asrc = g_Af + ((size_t)panel * 96 + c * 4) * 1024;
        #pragma unroll
        for (int i = 0; i < 4; i++) {
            int idx = t + i * 256;
            cp16(dst + idx * 16, Asrc + idx * 4);
        }
        #pragma unroll
        for (int j = 0; j < 4; j++) {
            const float* Bsrc = g_Wf + ((size_t)(c * 4 + j) * 2048 + nb0) * 64;
            #pragma unroll
            for (int i = 0; i < 2; i++) {
                int idx = t + i * 256;
                cp16(dst + B_IN_STAGE + j * 8192 + idx * 16, Bsrc + idx * 4);
            }
        }
    };

    auto loadFrags = [&](int slot, int k8, uint32_t a[4][4], uint32_t b[8][2]) {
        const float4* Aq = (const float4*)(smem + slot * STAGE_BYTES);
        const float2* Bp = (const float2*)(smem + slot * STAGE_BYTES + B_IN_STAGE);
        #pragma unroll
        for (int mt = 0; mt < 4; mt++) {
            float4 q = Aq[k8 * 256 + (wm * 4 + mt) * 32 + lane];
            a[mt][0] = __float_as_uint(q.x); a[mt][1] = __float_as_uint(q.y);
            a[mt][2] = __float_as_uint(q.z); a[mt][3] = __float_as_uint(q.w);
        }
        #pragma unroll
        for (int nt = 0; nt < 8; nt++) {
            float2 p2 = Bp[k8 * 1024 + (wn * 8 + nt) * 32 + lane];
            b[nt][0] = __float_as_uint(p2.x); b[nt][1] = __float_as_uint(p2.y);
        }
    };

    float acc[4][8][4];
    #pragma unroll
    for (int mt = 0; mt < 4; mt++)
        #pragma unroll
        for (int nt = 0; nt < 8; nt++)
            #pragma unroll
            for (int q = 0; q < 4; q++) acc[mt][nt][q] = 0.f;

    uint32_t aF[2][4][4], bF[2][8][2];

    issue(0, 0); CP_COMMIT();
    issue(1, 1); CP_COMMIT();
    CP_WAIT1();
    __syncthreads();
    loadFrags(0, 0, aF[0], bF[0]);

    int pp = 0;
    for (int c = 0; c < NCHUNK; c++) {
        int slot = c % NSTAGE;
        #pragma unroll
        for (int k8 = 0; k8 < 4; k8++) {
            int nxt = pp ^ 1;
            if (k8 < 3) {
                loadFrags(slot, k8 + 1, aF[nxt], bF[nxt]);
            } else if (c + 1 < NCHUNK) {
                if (c + 2 < NCHUNK) issue(c + 2, (c + 2) % NSTAGE);
                CP_COMMIT();
                CP_WAIT1();
                __syncthreads();
                loadFrags((c + 1) % NSTAGE, 0, aF[nxt], bF[nxt]);
            }
            #pragma unroll
            for (int mt = 0; mt < 4; mt++)
                #pragma unroll
                for (int nt = 0; nt < 8; nt++)
                    mma_tf32(acc[mt][nt], aF[pp][mt], bF[pp][nt]);
            pp ^= 1;
        }
    }

    #pragma unroll
    for (int mt = 0; mt < 4; mt++) {
        int m = m0 + wm * 64 + mt * 16 + r4;
        #pragma unroll
        for (int nt = 0; nt < 8; nt++) {
            int n = n0 + wn * 64 + nt * 8 + cs * 2;
            float2 bb = *(const float2*)(lat_bias + n);
            float2 v0 = make_float2(acc[mt][nt][0] + bb.x, acc[mt][nt][1] + bb.y);
            float2 v1 = make_float2(acc[mt][nt][2] + bb.x, acc[mt][nt][3] + bb.y);
            *(float2*)(C + (size_t)m * L_DIM + n) = v0;
            *(float2*)(C + (size_t)(m + 8) * L_DIM + n) = v1;
        }
    }
}

// ============================ kernel 4: top-k with exact boundary refinement ============================
__global__ void __launch_bounds__(256) topk_kernel(const float* __restrict__ P,
                                                   const float* __restrict__ lat_bias,
                                                   float* __restrict__ latents) {
    extern __shared__ uint32_t keys[];  // 16384 u32 = 64KB
    __shared__ int s_red[9];
    __shared__ int s_cnt_sel, s_cnt_eq, s_cnt_unc, s_cnt_fin;
    __shared__ uint32_t sel_key[K_TOP];
    __shared__ int      sel_idx[K_TOP];
    __shared__ uint32_t s_eqk[512];
    __shared__ int      s_eqi[512];
    __shared__ int      unc_idx[UNC_CAP];
    __shared__ float    unc_ex[UNC_CAP];
    __shared__ int      fin_idx[K_TOP];
    __shared__ float    fin_val[K_TOP];
    __shared__ uint32_t s_klo, s_khi;

    int row = blockIdx.x, t = threadIdx.x, lane = t & 31;
    const float* Pr = P + (size_t)row * L_DIM;

    #pragma unroll 8
    for (int i = 0; i < 64; i++)
        keys[t + (i << 8)] = float_to_key(Pr[t + (i << 8)]);
    if (t == 0) { s_cnt_sel = 0; s_cnt_eq = 0; s_cnt_unc = 0; s_cnt_fin = 0; }
    __syncthreads();

    uint32_t lo = 0, hi = 0xFFFFu;
    while (lo < hi) {
        uint32_t mid = lo + (hi - lo + 1) / 2;
        int c_local = 0;
        #pragma unroll 8
        for (int i = 0; i < 64; i++)
            c_local += (int)((keys[t + (i << 8)] >> 16) >= mid);
        for (int o = 16; o; o >>= 1) c_local += __shfl_down_sync(0xFFFFFFFFu, c_local, o);
        if ((t & 31) == 0) s_red[t >> 5] = c_local;
        __syncthreads();
        if (t < 32) {
            int v = (t < 8) ? s_red[t] : 0;
            for (int o = 4; o; o >>= 1) v += __shfl_down_sync(0xFFFFFFFFu, v, o);
            if (t == 0) s_red[8] = v;
        }
        __syncthreads();
        int total = s_red[8];
        __syncthreads();
        if (total >= K_TOP) lo = mid; else hi = mid - 1;
    }
    uint32_t T16 = lo;

    #pragma unroll 4
    for (int i = 0; i < 64; i++) {
        int idx = t + (i << 8);
        uint32_t k = keys[idx];
        uint32_t k16 = k >> 16;
        if (k16 > T16) {
            int p = atomicAdd(&s_cnt_sel, 1);
            sel_key[p] = k; sel_idx[p] = idx;
        } else if (k16 == T16) {
            int p = atomicAdd(&s_cnt_eq, 1);
            if (p < 512) { s_eqk[p] = k; s_eqi[p] = idx; }
        }
    }
    __syncthreads();
    if (t == 0) {
        int Ccnt = s_cnt_sel;
        int R = K_TOP - Ccnt;
        int E = s_cnt_eq < 512 ? s_cnt_eq : 512;
        for (int a = 1; a < E; a++) {
            uint32_t kk = s_eqk[a]; int ii = s_eqi[a]; int b = a - 1;
            while (b >= 0 && (s_eqk[b] < kk || (s_eqk[b] == kk && s_eqi[b] > ii))) {
                s_eqk[b + 1] = s_eqk[b]; s_eqi[b + 1] = s_eqi[b]; b--;
            }
            s_eqk[b + 1] = kk; s_eqi[b + 1] = ii;
        }
        for (int j = 0; j < R; j++) { sel_key[Ccnt + j] = s_eqk[j]; sel_idx[Ccnt + j] = s_eqi[j]; }
        float v100 = key_to_float(s_eqk[R - 1]);
        s_klo = float_to_key(v100 - DELTA_BAND);
        s_khi = float_to_key(v100 + DELTA_BAND);
    }
    __syncthreads();
    uint32_t klo = s_klo, khi = s_khi;

    #pragma unroll 4
    for (int i = 0; i < 64; i++) {
        int idx = t + (i << 8);
        uint32_t k = keys[idx];
        if (k >= klo && k <= khi) {
            int p = atomicAdd(&s_cnt_unc, 1);
            if (p < UNC_CAP) unc_idx[p] = idx;
        }
    }
    if (t < K_TOP) {
        if (sel_key[t] > khi) {
            int p = atomicAdd(&s_cnt_fin, 1);
            fin_idx[p] = sel_idx[t]; fin_val[p] = key_to_float(sel_key[t]);
        }
    }
    __syncthreads();
    int U = s_cnt_unc < UNC_CAP ? s_cnt_unc : UNC_CAP;
    int C = s_cnt_fin;
    int need = K_TOP - C; if (need > U) need = U;

    const float* Xr = g_Xb + (size_t)row * D_DIM;
    for (int c = (t >> 5); c < U; c += 8) {
        const float* w = g_WT + (size_t)unc_idx[c] * D_DIM;
        float s = 0.f, comp = 0.f;
        for (int d = lane; d < D_DIM; d += 32) {
            float prod = Xr[d] * w[d];
            float tn = s + prod;
            if (fabsf(s) >= fabsf(prod)) comp += (s - tn) + prod;
            else                         comp += (prod - tn) + s;
            s = tn;
        }
        s += comp;
        for (int o = 16; o; o >>= 1) s += __shfl_xor_sync(0xFFFFFFFFu, s, o);
        if (lane == 0) unc_ex[c] = s + lat_bias[unc_idx[c]];
    }
    __syncthreads();
    if (t == 0) {
        for (int a = 1; a < U; a++) {
            float vv = unc_ex[a]; int ii = unc_idx[a]; int b = a - 1;
            while (b >= 0 && (unc_ex[b] < vv || (unc_ex[b] == vv && unc_idx[b] > ii))) {
                unc_ex[b + 1] = unc_ex[b]; unc_idx[b + 1] = unc_idx[b]; b--;
            }
            unc_ex[b + 1] = vv; unc_idx[b + 1] = ii;
        }
        for (int q = 0; q < need; q++) {
            fin_idx[C + q] = unc_idx[q]; fin_val[C + q] = unc_ex[q];
        }
        s_cnt_fin = C + need;
    }
    __syncthreads();

    int F = s_cnt_fin;
    if (t < F) {
        int my = fin_idx[t]; float v = fin_val[t];
        int r = 0;
        for (int q = 0; q < F; q++) r += (int)(fin_idx[q] < my);
        g_tidx[row * K_TOP + r] = my;
        g_tval[row * K_TOP + r] = v;
        latents[(size_t)row * L_DIM + my] = v;
    }
}

// ============================ kernel 5: sparse decode ============================
__global__ void __launch_bounds__(256) decode_kernel(const float* __restrict__ Wd,
                                                     const float* __restrict__ pre_bias,
                                                     float* __restrict__ recons) {
    __shared__ int sidx[K_TOP];
    __shared__ float sval[K_TOP];
    int row = blockIdx.x, t = threadIdx.x;
    if (t < K_TOP) { sidx[t] = g_tidx[row * K_TOP + t]; sval[t] = g_tval[row * K_TOP + t]; }
    __syncthreads();
    float a0 = 0.f, a1 = 0.f, a2 = 0.f;
    #pragma unroll 4
    for (int j = 0; j < K_TOP; j++) {
        const float* w = Wd + (size_t)sidx[j] * D_DIM;
        float v = sval[j];
        a0 += v * __ldg(w + t);
        a1 += v * __ldg(w + t + 256);
        a2 += v * __ldg(w + t + 512);
    }
    float sd = g_std[row], mu = g_mu[row];
    float* Rr = recons + (size_t)row * D_DIM;
    Rr[t]       = (a0 + pre_bias[t])       * sd + mu;
    Rr[t + 256] = (a1 + pre_bias[t + 256]) * sd + mu;
    Rr[t + 512] = (a2 + pre_bias[t + 512]) * sd + mu;
}

// ============================ launch ============================
extern "C" void kernel_launch(void* const* d_in, const int* in_sizes, int n_in,
                              void* d_out, int out_size) {
    const float* x        = (const float*)d_in[0];
    const float* pre_bias = (const float*)d_in[1];
    const float* lat_bias = (const float*)d_in[2];
    const float* W_enc    = (const float*)d_in[3];
    const float* W_dec    = (const float*)d_in[4];

    float* outP = (float*)d_out;
    float* outL = outP + (size_t)B_DIM * L_DIM;
    float* outR = outL + (size_t)B_DIM * L_DIM;

    cudaFuncSetAttribute(gemm_kernel, cudaFuncAttributeMaxDynamicSharedMemorySize, GEMM_SMEM);
    cudaFuncSetAttribute(topk_kernel, cudaFuncAttributeMaxDynamicSharedMemorySize, 65536);

    normalize_kernel<<<B_DIM, 256>>>(x, pre_bias);
    packW_kernel<<<dim3(96, 64), 256>>>(W_enc);
    transpose_kernel<<<dim3(L_DIM / 32, D_DIM / 32), 256>>>(W_enc);
    gemm_kernel<<<dim3(L_DIM / 256, B_DIM / 128), 256, GEMM_SMEM>>>(lat_bias, outP);
    cudaMemsetAsync(outL, 0, (size_t)B_DIM * L_DIM * sizeof(float), 0);
    topk_kernel<<<B_DIM, 256, 65536>>>(outP, lat_bias, outL);
    decode_kernel<<<B_DIM, 256>>>(W_dec, pre_bias, outR);
}